// round 7
// baseline (speedup 1.0000x reference)
#include <cuda_runtime.h>
#include <cuda_bf16.h>
#include <math.h>
#include <stdint.h>

#define NTOK 16384
#define NMASK 16383
#define CDIM 512
#define CFFD 2048

typedef __nv_bfloat16 bf16;

// ---------------- scratch (static device globals; no allocs) ----------------
__device__ float g_h[NTOK * CDIM];
__device__ float g_mod[6 * CDIM];
__device__ float g_siluc[CDIM];
__device__ bf16 g_hn_h[NTOK * CDIM], g_hn_l[NTOK * CDIM];
__device__ bf16 g_qkv_h[NTOK * 3 * CDIM], g_qkv_l[NTOK * 3 * CDIM];
__device__ bf16 g_attn_h[NTOK * CDIM], g_attn_l[NTOK * CDIM];
__device__ bf16 g_mlp_h[NTOK * CFFD], g_mlp_l[NTOK * CFFD];
// weights hi/lo: [qkv | proj | fc1 | fc2]
#define OFF_QKV 0
#define OFF_PROJ 6291456
#define OFF_FC1 8388608
#define OFF_FC2 16777216
__device__ bf16 g_wh[25165824], g_wl[25165824];

// ======================= helpers ============================================
#define MMA16816(acc, a, b0v, b1v)                                              \
    asm volatile(                                                               \
        "mma.sync.aligned.m16n8k16.row.col.f32.bf16.bf16.f32 "                  \
        "{%0,%1,%2,%3},{%4,%5,%6,%7},{%8,%9},{%0,%1,%2,%3};"                    \
        : "+f"((acc)[0]), "+f"((acc)[1]), "+f"((acc)[2]), "+f"((acc)[3])        \
        : "r"((a)[0]), "r"((a)[1]), "r"((a)[2]), "r"((a)[3]), "r"(b0v), "r"(b1v))

#define CP_ASYNC16(dst_u32, src_ptr) \
    asm volatile("cp.async.cg.shared.global [%0], [%1], 16;" :: "r"(dst_u32), "l"(src_ptr))
#define CP_COMMIT() asm volatile("cp.async.commit_group;")
#define CP_WAIT2() asm volatile("cp.async.wait_group 2;")

__device__ __forceinline__ uint32_t smem_u32(const void* p) {
    uint32_t a;
    asm("{ .reg .u64 t; cvta.to.shared.u64 t, %1; cvt.u32.u64 %0, t; }" : "=r"(a) : "l"(p));
    return a;
}

__device__ __forceinline__ uint32_t pack_split(float a, float b, uint32_t& lo) {
    __nv_bfloat162 h = __floats2bfloat162_rn(a, b);
    float ra = a - __bfloat162float(h.x);
    float rb = b - __bfloat162float(h.y);
    __nv_bfloat162 l = __floats2bfloat162_rn(ra, rb);
    lo = *(uint32_t*)&l;
    return *(uint32_t*)&h;
}

// weight / activation pre-split: fp32 -> bf16 hi + bf16 lo
__global__ void k_split(const float* __restrict__ src, bf16* __restrict__ dh,
                        bf16* __restrict__ dl, int n4) {
    int i = blockIdx.x * 256 + threadIdx.x;
    if (i >= n4) return;
    float4 v = ((const float4*)src)[i];
    uint2 hv, lv;
    hv.x = pack_split(v.x, v.y, lv.x);
    hv.y = pack_split(v.z, v.w, lv.y);
    ((uint2*)dh)[i] = hv;
    ((uint2*)dl)[i] = lv;
}

// ======================= split-bf16 HMMA GEMM (cp.async 4-stage) ============
// out(NxM) = A(NxK) @ W(MxK)^T; A,W pre-split (hi/lo bf16); fp32 acc.
// CTA 128x128, BK=32, 8 warps (2x4), warp tile 64x32. 4-stage cp.async pipe.
// EPI 0: split-write (qkv; scale 0.125 on cols<512)
// EPI 1: gelu then split-write
// EPI 2: outf += gate[col]*(acc+bias)   (fp32 RMW)
template <int EPI>
__global__ void __launch_bounds__(256, 1)
k_mma_gemm(const bf16* __restrict__ Ah, const bf16* __restrict__ Al,
           const bf16* __restrict__ Wh, const bf16* __restrict__ Wl,
           const float* __restrict__ bias, float* __restrict__ outf,
           bf16* __restrict__ oh, bf16* __restrict__ ol,
           const float* __restrict__ gate, int K, int M) {
    extern __shared__ uint32_t smw[];  // 4 stages x 4 tiles x 2560 words = 163840B

    const int tid = threadIdx.x;
    const int wid = tid >> 5;
    const int lane = tid & 31;
    const int g = lane >> 2;
    const int t = lane & 3;
    const int warp_m = wid >> 2;
    const int warp_n = wid & 3;

    const int m0 = blockIdx.y * 128;
    const int n0 = blockIdx.x * 128;

    const bf16* Ah_p = Ah + (long)m0 * K;
    const bf16* Al_p = Al + (long)m0 * K;
    const bf16* Bh_p = Wh + (long)n0 * K;
    const bf16* Bl_p = Wl + (long)n0 * K;
    const int NC = K >> 5;

    const uint32_t sbase = smem_u32(smw);
    // per-thread copy mapping: f = it*256 + tid ; r=f>>2, q=f&3 (2 its per tile)
    const int cr = tid >> 2, cq = tid & 3;

    float acc[4][4][4];
#pragma unroll
    for (int i = 0; i < 4; i++)
#pragma unroll
        for (int j = 0; j < 4; j++)
#pragma unroll
            for (int k = 0; k < 4; k++) acc[i][j][k] = 0.f;

    // issue cp.async for chunk c into stage s (each thread: 8 x 16B)
    auto cp_chunk = [&](int c, int s) {
        uint32_t st = sbase + s * 40960;
#pragma unroll
        for (int it = 0; it < 2; it++) {
            int r = cr + it * 64;
            long go = (long)r * K + c * 32 + cq * 8;
            uint32_t so = st + (uint32_t)(r * 80 + cq * 16);
            CP_ASYNC16(so, Ah_p + go);
            CP_ASYNC16(so + 10240, Al_p + go);
            CP_ASYNC16(so + 20480, Bh_p + go);
            CP_ASYNC16(so + 30720, Bl_p + go);
        }
    };

    auto compute = [&](int s) {
        const uint32_t* sAh = smw + s * 10240;
        const uint32_t* sAl = sAh + 2560;
        const uint32_t* sBh = sAl + 2560;
        const uint32_t* sBl = sBh + 2560;
#pragma unroll
        for (int ks = 0; ks < 2; ks++) {
            uint32_t ah[4][4], al[4][4];
#pragma unroll
            for (int mt = 0; mt < 4; mt++) {
                int base = (warp_m * 64 + mt * 16 + g) * 20 + ks * 8 + t;
                ah[mt][0] = sAh[base];     ah[mt][1] = sAh[base + 160];
                ah[mt][2] = sAh[base + 4]; ah[mt][3] = sAh[base + 164];
                al[mt][0] = sAl[base];     al[mt][1] = sAl[base + 160];
                al[mt][2] = sAl[base + 4]; al[mt][3] = sAl[base + 164];
            }
#pragma unroll
            for (int nt = 0; nt < 4; nt++) {
                int bb = (warp_n * 32 + nt * 8 + g) * 20 + ks * 8 + t;
                uint32_t bh0 = sBh[bb], bh1 = sBh[bb + 4];
                uint32_t bl0 = sBl[bb], bl1 = sBl[bb + 4];
#pragma unroll
                for (int mt = 0; mt < 4; mt++) {
                    MMA16816(acc[mt][nt], ah[mt], bh0, bh1);
                    MMA16816(acc[mt][nt], al[mt], bh0, bh1);
                    MMA16816(acc[mt][nt], ah[mt], bl0, bl1);
                }
            }
        }
    };

    // prologue: stages 0..2
    cp_chunk(0, 0); CP_COMMIT();
    cp_chunk(1, 1); CP_COMMIT();
    cp_chunk(2, 2); CP_COMMIT();

    for (int c = 0; c < NC; c++) {
        CP_WAIT2();          // chunk c's group complete (2 newer may be in flight)
        __syncthreads();     // all warps see stage c; stage (c-1)%4 free for reuse
        if (c + 3 < NC) cp_chunk(c + 3, (c + 3) & 3);
        CP_COMMIT();         // empty groups keep the wait arithmetic uniform
        compute(c & 3);
    }

    // ---- epilogue ----
#pragma unroll
    for (int mt = 0; mt < 4; mt++) {
#pragma unroll
        for (int nt = 0; nt < 4; nt++) {
            float* ac = acc[mt][nt];
            int row = m0 + warp_m * 64 + mt * 16 + g;
            int col = n0 + warp_n * 32 + nt * 8 + 2 * t;
            float b0 = __ldg(bias + col), b1 = __ldg(bias + col + 1);
            float v[4];
            v[0] = ac[0] + b0; v[1] = ac[1] + b1;
            v[2] = ac[2] + b0; v[3] = ac[3] + b1;
            if (EPI == 0) {
                if (col < 512) {
#pragma unroll
                    for (int e = 0; e < 4; e++) v[e] *= 0.125f;
                }
            }
            if (EPI == 1) {
#pragma unroll
                for (int e = 0; e < 4; e++) {
                    float x = v[e];
                    float x3 = x * x * x;
                    v[e] = 0.5f * x * (1.0f + tanhf(0.7978845608028654f * (x + 0.044715f * x3)));
                }
            }
            if (EPI == 2) {
                float* dp0 = outf + (long)row * M + col;
                float* dp1 = outf + (long)(row + 8) * M + col;
                float g0 = __ldg(gate + col), g1 = __ldg(gate + col + 1);
                float2 o0 = *(float2*)dp0;
                float2 o1 = *(float2*)dp1;
                o0.x += g0 * v[0]; o0.y += g1 * v[1];
                o1.x += g0 * v[2]; o1.y += g1 * v[3];
                *(float2*)dp0 = o0;
                *(float2*)dp1 = o1;
            } else {
                uint32_t lo0, lo1;
                uint32_t hi0 = pack_split(v[0], v[1], lo0);
                uint32_t hi1 = pack_split(v[2], v[3], lo1);
                *(uint32_t*)(oh + (long)row * M + col) = hi0;
                *(uint32_t*)(ol + (long)row * M + col) = lo0;
                *(uint32_t*)(oh + (long)(row + 8) * M + col) = hi1;
                *(uint32_t*)(ol + (long)(row + 8) * M + col) = lo1;
            }
        }
    }
}

// ======================= HMMA windowed flash attention ======================
// grid (qtile=8, head=8, window=16), 256 thr (8 warps), BQ=128, BKV=64, D=64.
// q pre-scaled by 0.125 at the qkv epilogue. 3-term split on QK and PV.
__global__ void __launch_bounds__(256, 1)
k_attn_mma(const bf16* __restrict__ qh, const bf16* __restrict__ ql,
           bf16* __restrict__ oh, bf16* __restrict__ ol, int shift) {
    extern __shared__ uint32_t sw[];
    uint32_t* Qh = sw;            // 128 rows x 36 words (72 bf16 pitch)
    uint32_t* Ql = Qh + 4608;
    uint32_t* Kh = Ql + 4608;     // 64 rows x 36 words
    uint32_t* Kl = Kh + 2304;
    uint32_t* Vh = Kl + 2304;     // 64 d-rows x 36 words (token-pair packed)
    uint32_t* Vl = Vh + 2304;

    const int tid = threadIdx.x;
    const int wid = tid >> 5;
    const int lane = tid & 31;
    const int g = lane >> 2;
    const int t = lane & 3;

    const int qt = blockIdx.x, hh = blockIdx.y, w = blockIdx.z;
    const int qbase = w * 1024 + qt * 128;
    const int r0 = wid * 16;

    // ---- load Q tile (rows 0..127) ----
    {
        int row = tid >> 1, hf = tid & 1;
        int tok = (qbase + row + shift) & NMASK;
        const uint4* ph = (const uint4*)(qh + (long)tok * 1536 + hh * 64 + hf * 32);
        const uint4* pl = (const uint4*)(ql + (long)tok * 1536 + hh * 64 + hf * 32);
        int wo = row * 36 + hf * 16;
#pragma unroll
        for (int q = 0; q < 4; q++) {
            *(uint4*)&Qh[wo + q * 4] = ph[q];
            *(uint4*)&Ql[wo + q * 4] = pl[q];
        }
    }

    float accO[8][4];
#pragma unroll
    for (int i = 0; i < 8; i++)
#pragma unroll
        for (int j = 0; j < 4; j++) accO[i][j] = 0.f;
    float m0 = -1e30f, m1 = -1e30f, l0 = 0.f, l1 = 0.f;

    for (int c = 0; c < 16; c++) {
        int j0 = c * 64;
        __syncthreads();
        // K chunk: rows 0..63, straight copy
        {
            int jr = tid >> 2, qf = tid & 3;
            int tok = (w * 1024 + j0 + jr + shift) & NMASK;
            const uint4* ph = (const uint4*)(qh + (long)tok * 1536 + 512 + hh * 64 + qf * 16);
            const uint4* pl = (const uint4*)(ql + (long)tok * 1536 + 512 + hh * 64 + qf * 16);
            int wo = jr * 36 + qf * 8;
            *(uint4*)&Kh[wo] = ph[0];
            *(uint4*)&Kh[wo + 4] = ph[1];
            *(uint4*)&Kl[wo] = pl[0];
            *(uint4*)&Kl[wo + 4] = pl[1];
        }
        // V chunk: transpose-pack Vt[d][token-pair]
        {
            int jp = tid & 31, dg = tid >> 5;
            int t0 = (w * 1024 + j0 + 2 * jp + shift) & NMASK;
            int t1 = (w * 1024 + j0 + 2 * jp + 1 + shift) & NMASK;
            long o0 = (long)t0 * 1536 + 1024 + hh * 64 + dg * 8;
            long o1 = (long)t1 * 1536 + 1024 + hh * 64 + dg * 8;
            uint4 vh0 = *(const uint4*)(qh + o0);
            uint4 vh1 = *(const uint4*)(qh + o1);
            uint4 vl0 = *(const uint4*)(ql + o0);
            uint4 vl1 = *(const uint4*)(ql + o1);
            const bf16* a0 = (const bf16*)&vh0;
            const bf16* a1 = (const bf16*)&vh1;
            const bf16* b0 = (const bf16*)&vl0;
            const bf16* b1 = (const bf16*)&vl1;
#pragma unroll
            for (int i = 0; i < 8; i++) {
                uint32_t pv, qv;
                ((bf16*)&pv)[0] = a0[i]; ((bf16*)&pv)[1] = a1[i];
                ((bf16*)&qv)[0] = b0[i]; ((bf16*)&qv)[1] = b1[i];
                Vh[(dg * 8 + i) * 36 + jp] = pv;
                Vl[(dg * 8 + i) * 36 + jp] = qv;
            }
        }
        __syncthreads();

        // ---- S = Q K^T (16x64 per warp), 3-term split ----
        float accS[8][4];
#pragma unroll
        for (int i = 0; i < 8; i++)
#pragma unroll
            for (int j = 0; j < 4; j++) accS[i][j] = 0.f;
#pragma unroll
        for (int ks = 0; ks < 4; ks++) {
            uint32_t ah[4], al[4];
            int base = (r0 + g) * 36 + ks * 8 + t;
            int base8 = (r0 + g + 8) * 36 + ks * 8 + t;
            ah[0] = Qh[base]; ah[1] = Qh[base8]; ah[2] = Qh[base + 4]; ah[3] = Qh[base8 + 4];
            al[0] = Ql[base]; al[1] = Ql[base8]; al[2] = Ql[base + 4]; al[3] = Ql[base8 + 4];
#pragma unroll
            for (int nt = 0; nt < 8; nt++) {
                int bb = (nt * 8 + g) * 36 + ks * 8 + t;
                uint32_t bh0 = Kh[bb], bh1 = Kh[bb + 4];
                uint32_t bl0 = Kl[bb], bl1 = Kl[bb + 4];
                MMA16816(accS[nt], ah, bh0, bh1);
                MMA16816(accS[nt], al, bh0, bh1);
                MMA16816(accS[nt], ah, bl0, bl1);
            }
        }

        // ---- online softmax ----
        float ml0 = -1e30f, ml1 = -1e30f;
#pragma unroll
        for (int nt = 0; nt < 8; nt++) {
            ml0 = fmaxf(ml0, fmaxf(accS[nt][0], accS[nt][1]));
            ml1 = fmaxf(ml1, fmaxf(accS[nt][2], accS[nt][3]));
        }
#pragma unroll
        for (int off = 1; off < 4; off <<= 1) {
            ml0 = fmaxf(ml0, __shfl_xor_sync(0xffffffffu, ml0, off));
            ml1 = fmaxf(ml1, __shfl_xor_sync(0xffffffffu, ml1, off));
        }
        float mn0 = fmaxf(m0, ml0), mn1 = fmaxf(m1, ml1);
        float alpha0 = __expf(m0 - mn0), alpha1 = __expf(m1 - mn1);
        m0 = mn0; m1 = mn1;
        float rs0 = 0.f, rs1 = 0.f;
#pragma unroll
        for (int nt = 0; nt < 8; nt++) {
            accS[nt][0] = __expf(accS[nt][0] - mn0);
            accS[nt][1] = __expf(accS[nt][1] - mn0);
            accS[nt][2] = __expf(accS[nt][2] - mn1);
            accS[nt][3] = __expf(accS[nt][3] - mn1);
            rs0 += accS[nt][0] + accS[nt][1];
            rs1 += accS[nt][2] + accS[nt][3];
        }
#pragma unroll
        for (int off = 1; off < 4; off <<= 1) {
            rs0 += __shfl_xor_sync(0xffffffffu, rs0, off);
            rs1 += __shfl_xor_sync(0xffffffffu, rs1, off);
        }
        l0 = l0 * alpha0 + rs0;
        l1 = l1 * alpha1 + rs1;
#pragma unroll
        for (int nt = 0; nt < 8; nt++) {
            accO[nt][0] *= alpha0; accO[nt][1] *= alpha0;
            accO[nt][2] *= alpha1; accO[nt][3] *= alpha1;
        }

        // ---- O += P V (P split in registers) ----
#pragma unroll
        for (int kt = 0; kt < 4; kt++) {
            uint32_t ph[4], pl[4];
            ph[0] = pack_split(accS[2 * kt][0], accS[2 * kt][1], pl[0]);
            ph[1] = pack_split(accS[2 * kt][2], accS[2 * kt][3], pl[1]);
            ph[2] = pack_split(accS[2 * kt + 1][0], accS[2 * kt + 1][1], pl[2]);
            ph[3] = pack_split(accS[2 * kt + 1][2], accS[2 * kt + 1][3], pl[3]);
#pragma unroll
            for (int nt = 0; nt < 8; nt++) {
                int vb = (nt * 8 + g) * 36 + kt * 8 + t;
                uint32_t vh0 = Vh[vb], vh1 = Vh[vb + 4];
                uint32_t vl0 = Vl[vb], vl1 = Vl[vb + 4];
                MMA16816(accO[nt], ph, vh0, vh1);
                MMA16816(accO[nt], pl, vh0, vh1);
                MMA16816(accO[nt], ph, vl0, vl1);
            }
        }
    }

    // ---- finalize + split write ----
    float inv0 = 1.0f / l0, inv1 = 1.0f / l1;
    int tokA = (qbase + r0 + g + shift) & NMASK;
    int tokB = (qbase + r0 + g + 8 + shift) & NMASK;
#pragma unroll
    for (int nt = 0; nt < 8; nt++) {
        int col = hh * 64 + nt * 8 + 2 * t;
        uint32_t loA, loB;
        uint32_t hiA = pack_split(accO[nt][0] * inv0, accO[nt][1] * inv0, loA);
        uint32_t hiB = pack_split(accO[nt][2] * inv1, accO[nt][3] * inv1, loB);
        *(uint32_t*)(oh + (long)tokA * CDIM + col) = hiA;
        *(uint32_t*)(ol + (long)tokA * CDIM + col) = loA;
        *(uint32_t*)(oh + (long)tokB * CDIM + col) = hiB;
        *(uint32_t*)(ol + (long)tokB * CDIM + col) = loB;
    }
}

// ---------------- input embed ------------------------------------------------
__global__ void k_init(const float* __restrict__ feats, const int* __restrict__ coords,
                       const float* __restrict__ in_w, const float* __restrict__ in_b,
                       float* __restrict__ h) {
    int n = blockIdx.x;
    int tid = threadIdx.x;  // 256
    __shared__ float f[8];
    __shared__ int cd[3];
    if (tid < 8) f[tid] = feats[n * 8 + tid];
    if (tid < 3) cd[tid] = coords[n * 3 + tid];
    __syncthreads();
    for (int c = tid; c < CDIM; c += 256) {
        float acc = in_b[c];
#pragma unroll
        for (int i = 0; i < 8; i++) acc += f[i] * in_w[c * 8 + i];
        if (c < 510) {
            int j = c / 170;
            int k = c - j * 170;
            int kk = (k < 85) ? k : k - 85;
            float freq = expf((float)kk * (-9.210340371976184f / 85.0f));
            float o = (float)cd[j] * freq;
            acc += (k < 85) ? sinf(o) : cosf(o);
        }
        h[(long)n * CDIM + c] = acc;
    }
}

// ---------------- t embedding -> silu(c) ------------------------------------
__global__ void k_tembed(const float* __restrict__ t,
                         const float* __restrict__ w1, const float* __restrict__ b1,
                         const float* __restrict__ w2, const float* __restrict__ b2,
                         float* __restrict__ siluc) {
    __shared__ float emb[256];
    __shared__ float hid[512];
    int tid = threadIdx.x;  // 256
    float tv = t[0];
    if (tid < 128) {
        float fr = expf((float)tid * (-9.210340371976184f / 128.0f));
        float a = tv * fr;
        emb[tid] = cosf(a);
        emb[128 + tid] = sinf(a);
    }
    __syncthreads();
    for (int c = tid; c < 512; c += 256) {
        float acc = b1[c];
        const float* wr = w1 + (long)c * 256;
        for (int k = 0; k < 256; k++) acc += emb[k] * wr[k];
        hid[c] = acc / (1.0f + expf(-acc));
    }
    __syncthreads();
    for (int c = tid; c < 512; c += 256) {
        float acc = b2[c];
        const float* wr = w2 + (long)c * 512;
        for (int k = 0; k < 512; k++) acc += hid[k] * wr[k];
        siluc[c] = acc / (1.0f + expf(-acc));
    }
}

// ---------------- adaLN modulation ------------------------------------------
__global__ void k_ada(const float* __restrict__ siluc, const float* __restrict__ ada_w,
                      const float* __restrict__ ada_b, float* __restrict__ mod) {
    __shared__ float sc[512];
    int tid = threadIdx.x;  // 256
    for (int c = tid; c < 512; c += 256) sc[c] = siluc[c];
    __syncthreads();
    int warp = tid >> 5, lane = tid & 31;
    int m = blockIdx.x * 8 + warp;
    const float* wr = ada_w + (long)m * 512;
    float acc = 0.f;
    for (int k = lane; k < 512; k += 32) acc += sc[k] * wr[k];
#pragma unroll
    for (int off = 16; off; off >>= 1) acc += __shfl_xor_sync(0xffffffffu, acc, off);
    if (lane == 0) mod[m] = acc + ada_b[m];
}

// ---------------- LN + modulation -> split bf16 ------------------------------
__global__ void k_modln(const float* __restrict__ h, bf16* __restrict__ hn_h,
                        bf16* __restrict__ hn_l, const float* __restrict__ mod,
                        int sc_off, int sm_off) {
    int n = blockIdx.x;
    int tid = threadIdx.x;  // 128
    const float4* hp = (const float4*)(h + (long)n * CDIM);
    float4 x = hp[tid];
    float s = x.x + x.y + x.z + x.w;
    float sq = x.x * x.x + x.y * x.y + x.z * x.z + x.w * x.w;
#pragma unroll
    for (int off = 16; off; off >>= 1) {
        s += __shfl_xor_sync(0xffffffffu, s, off);
        sq += __shfl_xor_sync(0xffffffffu, sq, off);
    }
    __shared__ float rs[4], rq[4];
    int warp = tid >> 5;
    if ((tid & 31) == 0) { rs[warp] = s; rq[warp] = sq; }
    __syncthreads();
    float S = rs[0] + rs[1] + rs[2] + rs[3];
    float SQ = rq[0] + rq[1] + rq[2] + rq[3];
    float mean = S * (1.0f / 512.0f);
    float var = SQ * (1.0f / 512.0f) - mean * mean;
    float inv = rsqrtf(var + 1e-6f);
    int c = tid * 4;
    float4 scv = *(const float4*)(mod + sc_off + c);
    float4 smv = *(const float4*)(mod + sm_off + c);
    float o0 = (x.x - mean) * inv * (1.0f + scv.x) + smv.x;
    float o1 = (x.y - mean) * inv * (1.0f + scv.y) + smv.y;
    float o2 = (x.z - mean) * inv * (1.0f + scv.z) + smv.z;
    float o3 = (x.w - mean) * inv * (1.0f + scv.w) + smv.w;
    uint2 hv, lv;
    hv.x = pack_split(o0, o1, lv.x);
    hv.y = pack_split(o2, o3, lv.y);
    *(uint2*)(hn_h + (long)n * CDIM + c) = hv;
    *(uint2*)(hn_l + (long)n * CDIM + c) = lv;
}

// ---------------- output head ------------------------------------------------
__global__ void k_final(const float* __restrict__ h, const float* __restrict__ out_w,
                        const float* __restrict__ out_b, float* __restrict__ out) {
    int warp = threadIdx.x >> 5, lane = threadIdx.x & 31;
    int n = blockIdx.x * 8 + warp;
    const float* hp = h + (long)n * CDIM;
    float acc[8];
#pragma unroll
    for (int o = 0; o < 8; o++) acc[o] = 0.f;
    for (int c = lane; c < CDIM; c += 32) {
        float hv = hp[c];
#pragma unroll
        for (int o = 0; o < 8; o++) acc[o] += hv * out_w[o * CDIM + c];
    }
#pragma unroll
    for (int off = 16; off; off >>= 1)
#pragma unroll
        for (int o = 0; o < 8; o++) acc[o] += __shfl_xor_sync(0xffffffffu, acc[o], off);
    if (lane == 0)
#pragma unroll
        for (int o = 0; o < 8; o++) out[(long)n * 8 + o] = acc[o] + out_b[o];
}

// ---------------- launch ----------------------------------------------------
extern "C" void kernel_launch(void* const* d_in, const int* in_sizes, int n_in,
                              void* d_out, int out_size) {
    const float* feats  = (const float*)d_in[0];
    const int*   coords = (const int*)d_in[1];
    const float* t      = (const float*)d_in[2];
    const float* in_w   = (const float*)d_in[3];
    const float* in_b   = (const float*)d_in[4];
    const float* t_w1   = (const float*)d_in[5];
    const float* t_b1   = (const float*)d_in[6];
    const float* t_w2   = (const float*)d_in[7];
    const float* t_b2   = (const float*)d_in[8];
    const float* qkv_w  = (const float*)d_in[9];
    const float* qkv_b  = (const float*)d_in[10];
    const float* proj_w = (const float*)d_in[11];
    const float* proj_b = (const float*)d_in[12];
    const float* ada_w  = (const float*)d_in[13];
    const float* ada_b  = (const float*)d_in[14];
    const float* fc1_w  = (const float*)d_in[15];
    const float* fc1_b  = (const float*)d_in[16];
    const float* fc2_w  = (const float*)d_in[17];
    const float* fc2_b  = (const float*)d_in[18];
    const float* out_w  = (const float*)d_in[19];
    const float* out_b  = (const float*)d_in[20];
    float* out = (float*)d_out;

    float *p_h, *p_mod, *p_siluc;
    bf16 *p_hnh, *p_hnl, *p_qh, *p_ql, *p_ah, *p_al, *p_mh, *p_ml, *p_wh, *p_wl;
    cudaGetSymbolAddress((void**)&p_h, g_h);
    cudaGetSymbolAddress((void**)&p_mod, g_mod);
    cudaGetSymbolAddress((void**)&p_siluc, g_siluc);
    cudaGetSymbolAddress((void**)&p_hnh, g_hn_h);
    cudaGetSymbolAddress((void**)&p_hnl, g_hn_l);
    cudaGetSymbolAddress((void**)&p_qh, g_qkv_h);
    cudaGetSymbolAddress((void**)&p_ql, g_qkv_l);
    cudaGetSymbolAddress((void**)&p_ah, g_attn_h);
    cudaGetSymbolAddress((void**)&p_al, g_attn_l);
    cudaGetSymbolAddress((void**)&p_mh, g_mlp_h);
    cudaGetSymbolAddress((void**)&p_ml, g_mlp_l);
    cudaGetSymbolAddress((void**)&p_wh, g_wh);
    cudaGetSymbolAddress((void**)&p_wl, g_wl);

    const int GSM = 163840;  // 4 stages x 40960B
    const int ASM = 73728;
    cudaFuncSetAttribute(k_mma_gemm<0>, cudaFuncAttributeMaxDynamicSharedMemorySize, GSM);
    cudaFuncSetAttribute(k_mma_gemm<1>, cudaFuncAttributeMaxDynamicSharedMemorySize, GSM);
    cudaFuncSetAttribute(k_mma_gemm<2>, cudaFuncAttributeMaxDynamicSharedMemorySize, GSM);
    cudaFuncSetAttribute(k_attn_mma, cudaFuncAttributeMaxDynamicSharedMemorySize, ASM);

    // weight pre-split (runs every call; part of graph)
    k_split<<<(6291456 / 4 + 255) / 256, 256>>>(qkv_w, p_wh + OFF_QKV, p_wl + OFF_QKV, 6291456 / 4);
    k_split<<<(2097152 / 4 + 255) / 256, 256>>>(proj_w, p_wh + OFF_PROJ, p_wl + OFF_PROJ, 2097152 / 4);
    k_split<<<(8388608 / 4 + 255) / 256, 256>>>(fc1_w, p_wh + OFF_FC1, p_wl + OFF_FC1, 8388608 / 4);
    k_split<<<(8388608 / 4 + 255) / 256, 256>>>(fc2_w, p_wh + OFF_FC2, p_wl + OFF_FC2, 8388608 / 4);

    k_init<<<NTOK, 256>>>(feats, coords, in_w, in_b, p_h);
    k_tembed<<<1, 256>>>(t, t_w1, t_b1, t_w2, t_b2, p_siluc);

    for (int i = 0; i < 8; i++) {
        int shift = (i & 1) * 512;
        k_ada<<<384, 256>>>(p_siluc, ada_w + (long)i * 3072 * 512, ada_b + (long)i * 3072, p_mod);
        // attention branch
        k_modln<<<NTOK, 128>>>(p_h, p_hnh, p_hnl, p_mod, 512, 0);
        k_mma_gemm<0><<<dim3(12, 128), 256, GSM>>>(
            p_hnh, p_hnl, p_wh + OFF_QKV + (long)i * 786432, p_wl + OFF_QKV + (long)i * 786432,
            qkv_b + (long)i * 1536, nullptr, p_qh, p_ql, nullptr, 512, 1536);
        k_attn_mma<<<dim3(8, 8, 16), 256, ASM>>>(p_qh, p_ql, p_ah, p_al, shift);
        k_mma_gemm<2><<<dim3(4, 128), 256, GSM>>>(
            p_ah, p_al, p_wh + OFF_PROJ + (long)i * 262144, p_wl + OFF_PROJ + (long)i * 262144,
            proj_b + (long)i * 512, p_h, nullptr, nullptr, p_mod + 1024, 512, 512);
        // mlp branch
        k_modln<<<NTOK, 128>>>(p_h, p_hnh, p_hnl, p_mod, 2048, 1536);
        k_mma_gemm<1><<<dim3(16, 128), 256, GSM>>>(
            p_hnh, p_hnl, p_wh + OFF_FC1 + (long)i * 1048576, p_wl + OFF_FC1 + (long)i * 1048576,
            fc1_b + (long)i * 2048, nullptr, p_mh, p_ml, nullptr, 512, 2048);
        k_mma_gemm<2><<<dim3(4, 128), 256, GSM>>>(
            p_mh, p_ml, p_wh + OFF_FC2 + (long)i * 1048576, p_wl + OFF_FC2 + (long)i * 1048576,
            fc2_b + (long)i * 512, p_h, nullptr, nullptr, p_mod + 2560, 2048, 512);
    }

    k_final<<<2048, 256>>>(p_h, out_w, out_b, out);
}

// round 8
// speedup vs baseline: 1.9637x; 1.9637x over previous
#include <cuda_runtime.h>
#include <cuda_fp16.h>
#include <math.h>
#include <stdint.h>

#define NTOK 16384
#define NMASK 16383
#define CDIM 512
#define CFFD 2048

typedef __half half_t;

// ---------------- scratch (static device globals; no allocs) ----------------
__device__ float g_h[NTOK * CDIM];
__device__ float g_mod[6 * CDIM];
__device__ float g_siluc[CDIM];
__device__ half_t g_hn[NTOK * CDIM];
__device__ half_t g_qkv[NTOK * 3 * CDIM];
__device__ half_t g_attn[NTOK * CDIM];
__device__ half_t g_mlp[NTOK * CFFD];
// weights fp16: [qkv | proj | fc1 | fc2]
#define OFF_QKV 0
#define OFF_PROJ 6291456
#define OFF_FC1 8388608
#define OFF_FC2 16777216
__device__ half_t g_w[25165824];

// ======================= helpers ============================================
#define MMA16816(acc, a, b0v, b1v)                                              \
    asm volatile(                                                               \
        "mma.sync.aligned.m16n8k16.row.col.f32.f16.f16.f32 "                    \
        "{%0,%1,%2,%3},{%4,%5,%6,%7},{%8,%9},{%0,%1,%2,%3};"                    \
        : "+f"((acc)[0]), "+f"((acc)[1]), "+f"((acc)[2]), "+f"((acc)[3])        \
        : "r"((a)[0]), "r"((a)[1]), "r"((a)[2]), "r"((a)[3]), "r"(b0v), "r"(b1v))

#define CP_ASYNC16(dst_u32, src_ptr) \
    asm volatile("cp.async.cg.shared.global [%0], [%1], 16;" :: "r"(dst_u32), "l"(src_ptr))
#define CP_COMMIT() asm volatile("cp.async.commit_group;")
#define CP_WAIT2() asm volatile("cp.async.wait_group 2;")

__device__ __forceinline__ uint32_t smem_u32(const void* p) {
    uint32_t a;
    asm("{ .reg .u64 t; cvta.to.shared.u64 t, %1; cvt.u32.u64 %0, t; }" : "=r"(a) : "l"(p));
    return a;
}

__device__ __forceinline__ uint32_t pack2(float a, float b) {
    __half2 h = __floats2half2_rn(a, b);
    return *(uint32_t*)&h;
}

// fp32 -> fp16 conversion
__global__ void k_half(const float* __restrict__ src, half_t* __restrict__ dst, int n4) {
    int i = blockIdx.x * 256 + threadIdx.x;
    if (i >= n4) return;
    float4 v = ((const float4*)src)[i];
    uint2 o;
    o.x = pack2(v.x, v.y);
    o.y = pack2(v.z, v.w);
    ((uint2*)dst)[i] = o;
}

// ======================= fp16 HMMA GEMM (cp.async 4-stage) ==================
// out(NxM) = A(NxK) @ W(MxK)^T; fp16 operands, fp32 acc.
// CTA 128x128, BK=32, 8 warps (2x4), warp tile 64x32.
// EPI 0: half-write (qkv; scale 0.125 on cols<512)
// EPI 1: gelu then half-write
// EPI 2: outf += gate[col]*(acc+bias)   (fp32 RMW)
template <int EPI>
__global__ void __launch_bounds__(256, 1)
k_mma_gemm(const half_t* __restrict__ A, const half_t* __restrict__ W,
           const float* __restrict__ bias, float* __restrict__ outf,
           half_t* __restrict__ oh, const float* __restrict__ gate, int K, int M) {
    extern __shared__ uint32_t smw[];  // 4 stages x (A+B) x 2560 words = 81920B

    const int tid = threadIdx.x;
    const int wid = tid >> 5;
    const int lane = tid & 31;
    const int g = lane >> 2;
    const int t = lane & 3;
    const int warp_m = wid >> 2;
    const int warp_n = wid & 3;

    const int m0 = blockIdx.y * 128;
    const int n0 = blockIdx.x * 128;

    const half_t* Ap = A + (long)m0 * K;
    const half_t* Bp = W + (long)n0 * K;
    const int NC = K >> 5;

    const uint32_t sbase = smem_u32(smw);
    const int cr = tid >> 2, cq = tid & 3;

    float acc[4][4][4];
#pragma unroll
    for (int i = 0; i < 4; i++)
#pragma unroll
        for (int j = 0; j < 4; j++)
#pragma unroll
            for (int k = 0; k < 4; k++) acc[i][j][k] = 0.f;

    // issue cp.async for chunk c into stage s (each thread: 4 x 16B)
    auto cp_chunk = [&](int c, int s) {
        uint32_t st = sbase + s * 20480;
#pragma unroll
        for (int it = 0; it < 2; it++) {
            int r = cr + it * 64;
            long go = (long)r * K + c * 32 + cq * 8;
            uint32_t so = st + (uint32_t)(r * 80 + cq * 16);
            CP_ASYNC16(so, Ap + go);
            CP_ASYNC16(so + 10240, Bp + go);
        }
    };

    auto compute = [&](int s) {
        const uint32_t* sA = smw + s * 5120;
        const uint32_t* sB = sA + 2560;
#pragma unroll
        for (int ks = 0; ks < 2; ks++) {
            uint32_t a[4][4];
#pragma unroll
            for (int mt = 0; mt < 4; mt++) {
                int base = (warp_m * 64 + mt * 16 + g) * 20 + ks * 8 + t;
                a[mt][0] = sA[base];     a[mt][1] = sA[base + 160];
                a[mt][2] = sA[base + 4]; a[mt][3] = sA[base + 164];
            }
#pragma unroll
            for (int nt = 0; nt < 4; nt++) {
                int bb = (warp_n * 32 + nt * 8 + g) * 20 + ks * 8 + t;
                uint32_t b0 = sB[bb], b1 = sB[bb + 4];
#pragma unroll
                for (int mt = 0; mt < 4; mt++) MMA16816(acc[mt][nt], a[mt], b0, b1);
            }
        }
    };

    cp_chunk(0, 0); CP_COMMIT();
    cp_chunk(1, 1); CP_COMMIT();
    cp_chunk(2, 2); CP_COMMIT();

    for (int c = 0; c < NC; c++) {
        CP_WAIT2();
        __syncthreads();
        if (c + 3 < NC) cp_chunk(c + 3, (c + 3) & 3);
        CP_COMMIT();
        compute(c & 3);
    }

    // ---- epilogue ----
#pragma unroll
    for (int mt = 0; mt < 4; mt++) {
#pragma unroll
        for (int nt = 0; nt < 4; nt++) {
            float* ac = acc[mt][nt];
            int row = m0 + warp_m * 64 + mt * 16 + g;
            int col = n0 + warp_n * 32 + nt * 8 + 2 * t;
            float b0 = __ldg(bias + col), b1 = __ldg(bias + col + 1);
            float v[4];
            v[0] = ac[0] + b0; v[1] = ac[1] + b1;
            v[2] = ac[2] + b0; v[3] = ac[3] + b1;
            if (EPI == 0) {
                if (col < 512) {
#pragma unroll
                    for (int e = 0; e < 4; e++) v[e] *= 0.125f;
                }
            }
            if (EPI == 1) {
#pragma unroll
                for (int e = 0; e < 4; e++) {
                    float x = v[e];
                    float x3 = x * x * x;
                    v[e] = 0.5f * x * (1.0f + tanhf(0.7978845608028654f * (x + 0.044715f * x3)));
                }
            }
            if (EPI == 2) {
                float* dp0 = outf + (long)row * M + col;
                float* dp1 = outf + (long)(row + 8) * M + col;
                float g0 = __ldg(gate + col), g1 = __ldg(gate + col + 1);
                float2 o0 = *(float2*)dp0;
                float2 o1 = *(float2*)dp1;
                o0.x += g0 * v[0]; o0.y += g1 * v[1];
                o1.x += g0 * v[2]; o1.y += g1 * v[3];
                *(float2*)dp0 = o0;
                *(float2*)dp1 = o1;
            } else {
                *(uint32_t*)(oh + (long)row * M + col) = pack2(v[0], v[1]);
                *(uint32_t*)(oh + (long)(row + 8) * M + col) = pack2(v[2], v[3]);
            }
        }
    }
}

// ======================= fp16 HMMA windowed flash attention =================
// grid (qtile=8, head=8, window=16), 256 thr (8 warps), BQ=128, BKV=64, D=64.
// q pre-scaled by 0.125 at the qkv epilogue.
__global__ void __launch_bounds__(256, 1)
k_attn_mma(const half_t* __restrict__ qkv, half_t* __restrict__ attn, int shift) {
    extern __shared__ uint32_t sw[];
    uint32_t* Qs = sw;            // 128 rows x 36 words (72 half pitch)
    uint32_t* Ks = Qs + 4608;     // 64 rows x 36 words
    uint32_t* Vs = Ks + 2304;     // 64 d-rows x 36 words (token-pair packed)

    const int tid = threadIdx.x;
    const int wid = tid >> 5;
    const int lane = tid & 31;
    const int g = lane >> 2;
    const int t = lane & 3;

    const int qt = blockIdx.x, hh = blockIdx.y, w = blockIdx.z;
    const int qbase = w * 1024 + qt * 128;
    const int r0 = wid * 16;

    // ---- load Q tile ----
    {
        int row = tid >> 1, hf = tid & 1;
        int tok = (qbase + row + shift) & NMASK;
        const uint4* p = (const uint4*)(qkv + (long)tok * 1536 + hh * 64 + hf * 32);
        int wo = row * 36 + hf * 16;
#pragma unroll
        for (int q = 0; q < 4; q++) *(uint4*)&Qs[wo + q * 4] = p[q];
    }

    float accO[8][4];
#pragma unroll
    for (int i = 0; i < 8; i++)
#pragma unroll
        for (int j = 0; j < 4; j++) accO[i][j] = 0.f;
    float m0 = -1e30f, m1 = -1e30f, l0 = 0.f, l1 = 0.f;

    for (int c = 0; c < 16; c++) {
        int j0 = c * 64;
        __syncthreads();
        // K chunk
        {
            int jr = tid >> 2, qf = tid & 3;
            int tok = (w * 1024 + j0 + jr + shift) & NMASK;
            const uint4* p = (const uint4*)(qkv + (long)tok * 1536 + 512 + hh * 64 + qf * 16);
            int wo = jr * 36 + qf * 8;
            *(uint4*)&Ks[wo] = p[0];
            *(uint4*)&Ks[wo + 4] = p[1];
        }
        // V chunk: transpose-pack Vt[d][token-pair]
        {
            int jp = tid & 31, dg = tid >> 5;
            int t0 = (w * 1024 + j0 + 2 * jp + shift) & NMASK;
            int t1 = (w * 1024 + j0 + 2 * jp + 1 + shift) & NMASK;
            uint4 v0 = *(const uint4*)(qkv + (long)t0 * 1536 + 1024 + hh * 64 + dg * 8);
            uint4 v1 = *(const uint4*)(qkv + (long)t1 * 1536 + 1024 + hh * 64 + dg * 8);
            const half_t* a0 = (const half_t*)&v0;
            const half_t* a1 = (const half_t*)&v1;
#pragma unroll
            for (int i = 0; i < 8; i++) {
                uint32_t pv;
                ((half_t*)&pv)[0] = a0[i];
                ((half_t*)&pv)[1] = a1[i];
                Vs[(dg * 8 + i) * 36 + jp] = pv;
            }
        }
        __syncthreads();

        // ---- S = Q K^T (16x64 per warp) ----
        float accS[8][4];
#pragma unroll
        for (int i = 0; i < 8; i++)
#pragma unroll
            for (int j = 0; j < 4; j++) accS[i][j] = 0.f;
#pragma unroll
        for (int ks = 0; ks < 4; ks++) {
            uint32_t a[4];
            int base = (r0 + g) * 36 + ks * 8 + t;
            int base8 = (r0 + g + 8) * 36 + ks * 8 + t;
            a[0] = Qs[base]; a[1] = Qs[base8]; a[2] = Qs[base + 4]; a[3] = Qs[base8 + 4];
#pragma unroll
            for (int nt = 0; nt < 8; nt++) {
                int bb = (nt * 8 + g) * 36 + ks * 8 + t;
                uint32_t b0 = Ks[bb], b1 = Ks[bb + 4];
                MMA16816(accS[nt], a, b0, b1);
            }
        }

        // ---- online softmax ----
        float ml0 = -1e30f, ml1 = -1e30f;
#pragma unroll
        for (int nt = 0; nt < 8; nt++) {
            ml0 = fmaxf(ml0, fmaxf(accS[nt][0], accS[nt][1]));
            ml1 = fmaxf(ml1, fmaxf(accS[nt][2], accS[nt][3]));
        }
#pragma unroll
        for (int off = 1; off < 4; off <<= 1) {
            ml0 = fmaxf(ml0, __shfl_xor_sync(0xffffffffu, ml0, off));
            ml1 = fmaxf(ml1, __shfl_xor_sync(0xffffffffu, ml1, off));
        }
        float mn0 = fmaxf(m0, ml0), mn1 = fmaxf(m1, ml1);
        float alpha0 = __expf(m0 - mn0), alpha1 = __expf(m1 - mn1);
        m0 = mn0; m1 = mn1;
        float rs0 = 0.f, rs1 = 0.f;
#pragma unroll
        for (int nt = 0; nt < 8; nt++) {
            accS[nt][0] = __expf(accS[nt][0] - mn0);
            accS[nt][1] = __expf(accS[nt][1] - mn0);
            accS[nt][2] = __expf(accS[nt][2] - mn1);
            accS[nt][3] = __expf(accS[nt][3] - mn1);
            rs0 += accS[nt][0] + accS[nt][1];
            rs1 += accS[nt][2] + accS[nt][3];
        }
#pragma unroll
        for (int off = 1; off < 4; off <<= 1) {
            rs0 += __shfl_xor_sync(0xffffffffu, rs0, off);
            rs1 += __shfl_xor_sync(0xffffffffu, rs1, off);
        }
        l0 = l0 * alpha0 + rs0;
        l1 = l1 * alpha1 + rs1;
#pragma unroll
        for (int nt = 0; nt < 8; nt++) {
            accO[nt][0] *= alpha0; accO[nt][1] *= alpha0;
            accO[nt][2] *= alpha1; accO[nt][3] *= alpha1;
        }

        // ---- O += P V ----
#pragma unroll
        for (int kt = 0; kt < 4; kt++) {
            uint32_t p[4];
            p[0] = pack2(accS[2 * kt][0], accS[2 * kt][1]);
            p[1] = pack2(accS[2 * kt][2], accS[2 * kt][3]);
            p[2] = pack2(accS[2 * kt + 1][0], accS[2 * kt + 1][1]);
            p[3] = pack2(accS[2 * kt + 1][2], accS[2 * kt + 1][3]);
#pragma unroll
            for (int nt = 0; nt < 8; nt++) {
                int vb = (nt * 8 + g) * 36 + kt * 8 + t;
                uint32_t v0 = Vs[vb], v1 = Vs[vb + 4];
                MMA16816(accO[nt], p, v0, v1);
            }
        }
    }

    // ---- finalize + write ----
    float inv0 = 1.0f / l0, inv1 = 1.0f / l1;
    int tokA = (qbase + r0 + g + shift) & NMASK;
    int tokB = (qbase + r0 + g + 8 + shift) & NMASK;
#pragma unroll
    for (int nt = 0; nt < 8; nt++) {
        int col = hh * 64 + nt * 8 + 2 * t;
        *(uint32_t*)(attn + (long)tokA * CDIM + col) = pack2(accO[nt][0] * inv0, accO[nt][1] * inv0);
        *(uint32_t*)(attn + (long)tokB * CDIM + col) = pack2(accO[nt][2] * inv1, accO[nt][3] * inv1);
    }
}

// ---------------- input embed ------------------------------------------------
__global__ void k_init(const float* __restrict__ feats, const int* __restrict__ coords,
                       const float* __restrict__ in_w, const float* __restrict__ in_b,
                       float* __restrict__ h) {
    int n = blockIdx.x;
    int tid = threadIdx.x;  // 256
    __shared__ float f[8];
    __shared__ int cd[3];
    if (tid < 8) f[tid] = feats[n * 8 + tid];
    if (tid < 3) cd[tid] = coords[n * 3 + tid];
    __syncthreads();
    for (int c = tid; c < CDIM; c += 256) {
        float acc = in_b[c];
#pragma unroll
        for (int i = 0; i < 8; i++) acc += f[i] * in_w[c * 8 + i];
        if (c < 510) {
            int j = c / 170;
            int k = c - j * 170;
            int kk = (k < 85) ? k : k - 85;
            float freq = expf((float)kk * (-9.210340371976184f / 85.0f));
            float o = (float)cd[j] * freq;
            acc += (k < 85) ? sinf(o) : cosf(o);
        }
        h[(long)n * CDIM + c] = acc;
    }
}

// ---------------- t embedding -> silu(c) ------------------------------------
__global__ void k_tembed(const float* __restrict__ t,
                         const float* __restrict__ w1, const float* __restrict__ b1,
                         const float* __restrict__ w2, const float* __restrict__ b2,
                         float* __restrict__ siluc) {
    __shared__ float emb[256];
    __shared__ float hid[512];
    int tid = threadIdx.x;  // 256
    float tv = t[0];
    if (tid < 128) {
        float fr = expf((float)tid * (-9.210340371976184f / 128.0f));
        float a = tv * fr;
        emb[tid] = cosf(a);
        emb[128 + tid] = sinf(a);
    }
    __syncthreads();
    for (int c = tid; c < 512; c += 256) {
        float acc = b1[c];
        const float* wr = w1 + (long)c * 256;
        for (int k = 0; k < 256; k++) acc += emb[k] * wr[k];
        hid[c] = acc / (1.0f + expf(-acc));
    }
    __syncthreads();
    for (int c = tid; c < 512; c += 256) {
        float acc = b2[c];
        const float* wr = w2 + (long)c * 512;
        for (int k = 0; k < 512; k++) acc += hid[k] * wr[k];
        siluc[c] = acc / (1.0f + expf(-acc));
    }
}

// ---------------- adaLN modulation ------------------------------------------
__global__ void k_ada(const float* __restrict__ siluc, const float* __restrict__ ada_w,
                      const float* __restrict__ ada_b, float* __restrict__ mod) {
    __shared__ float sc[512];
    int tid = threadIdx.x;  // 256
    for (int c = tid; c < 512; c += 256) sc[c] = siluc[c];
    __syncthreads();
    int warp = tid >> 5, lane = tid & 31;
    int m = blockIdx.x * 8 + warp;
    const float* wr = ada_w + (long)m * 512;
    float acc = 0.f;
    for (int k = lane; k < 512; k += 32) acc += sc[k] * wr[k];
#pragma unroll
    for (int off = 16; off; off >>= 1) acc += __shfl_xor_sync(0xffffffffu, acc, off);
    if (lane == 0) mod[m] = acc + ada_b[m];
}

// ---------------- LN + modulation -> fp16 ------------------------------------
__global__ void k_modln(const float* __restrict__ h, half_t* __restrict__ hn,
                        const float* __restrict__ mod, int sc_off, int sm_off) {
    int n = blockIdx.x;
    int tid = threadIdx.x;  // 128
    const float4* hp = (const float4*)(h + (long)n * CDIM);
    float4 x = hp[tid];
    float s = x.x + x.y + x.z + x.w;
    float sq = x.x * x.x + x.y * x.y + x.z * x.z + x.w * x.w;
#pragma unroll
    for (int off = 16; off; off >>= 1) {
        s += __shfl_xor_sync(0xffffffffu, s, off);
        sq += __shfl_xor_sync(0xffffffffu, sq, off);
    }
    __shared__ float rs[4], rq[4];
    int warp = tid >> 5;
    if ((tid & 31) == 0) { rs[warp] = s; rq[warp] = sq; }
    __syncthreads();
    float S = rs[0] + rs[1] + rs[2] + rs[3];
    float SQ = rq[0] + rq[1] + rq[2] + rq[3];
    float mean = S * (1.0f / 512.0f);
    float var = SQ * (1.0f / 512.0f) - mean * mean;
    float inv = rsqrtf(var + 1e-6f);
    int c = tid * 4;
    float4 scv = *(const float4*)(mod + sc_off + c);
    float4 smv = *(const float4*)(mod + sm_off + c);
    float o0 = (x.x - mean) * inv * (1.0f + scv.x) + smv.x;
    float o1 = (x.y - mean) * inv * (1.0f + scv.y) + smv.y;
    float o2 = (x.z - mean) * inv * (1.0f + scv.z) + smv.z;
    float o3 = (x.w - mean) * inv * (1.0f + scv.w) + smv.w;
    uint2 o;
    o.x = pack2(o0, o1);
    o.y = pack2(o2, o3);
    *(uint2*)(hn + (long)n * CDIM + c) = o;
}

// ---------------- output head ------------------------------------------------
__global__ void k_final(const float* __restrict__ h, const float* __restrict__ out_w,
                        const float* __restrict__ out_b, float* __restrict__ out) {
    int warp = threadIdx.x >> 5, lane = threadIdx.x & 31;
    int n = blockIdx.x * 8 + warp;
    const float* hp = h + (long)n * CDIM;
    float acc[8];
#pragma unroll
    for (int o = 0; o < 8; o++) acc[o] = 0.f;
    for (int c = lane; c < CDIM; c += 32) {
        float hv = hp[c];
#pragma unroll
        for (int o = 0; o < 8; o++) acc[o] += hv * out_w[o * CDIM + c];
    }
#pragma unroll
    for (int off = 16; off; off >>= 1)
#pragma unroll
        for (int o = 0; o < 8; o++) acc[o] += __shfl_xor_sync(0xffffffffu, acc[o], off);
    if (lane == 0)
#pragma unroll
        for (int o = 0; o < 8; o++) out[(long)n * 8 + o] = acc[o] + out_b[o];
}

// ---------------- launch ----------------------------------------------------
extern "C" void kernel_launch(void* const* d_in, const int* in_sizes, int n_in,
                              void* d_out, int out_size) {
    const float* feats  = (const float*)d_in[0];
    const int*   coords = (const int*)d_in[1];
    const float* t      = (const float*)d_in[2];
    const float* in_w   = (const float*)d_in[3];
    const float* in_b   = (const float*)d_in[4];
    const float* t_w1   = (const float*)d_in[5];
    const float* t_b1   = (const float*)d_in[6];
    const float* t_w2   = (const float*)d_in[7];
    const float* t_b2   = (const float*)d_in[8];
    const float* qkv_w  = (const float*)d_in[9];
    const float* qkv_b  = (const float*)d_in[10];
    const float* proj_w = (const float*)d_in[11];
    const float* proj_b = (const float*)d_in[12];
    const float* ada_w  = (const float*)d_in[13];
    const float* ada_b  = (const float*)d_in[14];
    const float* fc1_w  = (const float*)d_in[15];
    const float* fc1_b  = (const float*)d_in[16];
    const float* fc2_w  = (const float*)d_in[17];
    const float* fc2_b  = (const float*)d_in[18];
    const float* out_w  = (const float*)d_in[19];
    const float* out_b  = (const float*)d_in[20];
    float* out = (float*)d_out;

    float *p_h, *p_mod, *p_siluc;
    half_t *p_hn, *p_q, *p_a, *p_m, *p_w;
    cudaGetSymbolAddress((void**)&p_h, g_h);
    cudaGetSymbolAddress((void**)&p_mod, g_mod);
    cudaGetSymbolAddress((void**)&p_siluc, g_siluc);
    cudaGetSymbolAddress((void**)&p_hn, g_hn);
    cudaGetSymbolAddress((void**)&p_q, g_qkv);
    cudaGetSymbolAddress((void**)&p_a, g_attn);
    cudaGetSymbolAddress((void**)&p_m, g_mlp);
    cudaGetSymbolAddress((void**)&p_w, g_w);

    const int GSM = 81920;  // 4 stages x 20480B
    const int ASM = 36864;  // Q 4608 + K 2304 + V 2304 words
    cudaFuncSetAttribute(k_mma_gemm<0>, cudaFuncAttributeMaxDynamicSharedMemorySize, GSM);
    cudaFuncSetAttribute(k_mma_gemm<1>, cudaFuncAttributeMaxDynamicSharedMemorySize, GSM);
    cudaFuncSetAttribute(k_mma_gemm<2>, cudaFuncAttributeMaxDynamicSharedMemorySize, GSM);
    cudaFuncSetAttribute(k_attn_mma, cudaFuncAttributeMaxDynamicSharedMemorySize, ASM);

    // weight fp16 conversion (runs every call; part of graph)
    k_half<<<(6291456 / 4 + 255) / 256, 256>>>(qkv_w, p_w + OFF_QKV, 6291456 / 4);
    k_half<<<(2097152 / 4 + 255) / 256, 256>>>(proj_w, p_w + OFF_PROJ, 2097152 / 4);
    k_half<<<(8388608 / 4 + 255) / 256, 256>>>(fc1_w, p_w + OFF_FC1, 8388608 / 4);
    k_half<<<(8388608 / 4 + 255) / 256, 256>>>(fc2_w, p_w + OFF_FC2, 8388608 / 4);

    k_init<<<NTOK, 256>>>(feats, coords, in_w, in_b, p_h);
    k_tembed<<<1, 256>>>(t, t_w1, t_b1, t_w2, t_b2, p_siluc);

    for (int i = 0; i < 8; i++) {
        int shift = (i & 1) * 512;
        k_ada<<<384, 256>>>(p_siluc, ada_w + (long)i * 3072 * 512, ada_b + (long)i * 3072, p_mod);
        // attention branch
        k_modln<<<NTOK, 128>>>(p_h, p_hn, p_mod, 512, 0);
        k_mma_gemm<0><<<dim3(12, 128), 256, GSM>>>(
            p_hn, p_w + OFF_QKV + (long)i * 786432, qkv_b + (long)i * 1536,
            nullptr, p_q, nullptr, 512, 1536);
        k_attn_mma<<<dim3(8, 8, 16), 256, ASM>>>(p_q, p_a, shift);
        k_mma_gemm<2><<<dim3(4, 128), 256, GSM>>>(
            p_a, p_w + OFF_PROJ + (long)i * 262144, proj_b + (long)i * 512,
            p_h, nullptr, p_mod + 1024, 512, 512);
        // mlp branch
        k_modln<<<NTOK, 128>>>(p_h, p_hn, p_mod, 2048, 1536);
        k_mma_gemm<1><<<dim3(16, 128), 256, GSM>>>(
            p_hn, p_w + OFF_FC1 + (long)i * 1048576, fc1_b + (long)i * 2048,
            nullptr, p_m, nullptr, 512, 2048);
        k_mma_gemm<2><<<dim3(4, 128), 256, GSM>>>(
            p_m, p_w + OFF_FC2 + (long)i * 1048576, fc2_b + (long)i * 512,
            p_h, nullptr, p_mod + 2560, 2048, 512);
    }

    k_final<<<2048, 256>>>(p_h, out_w, out_b, out);
}